// round 1
// baseline (speedup 1.0000x reference)
#include <cuda_runtime.h>
#include <math.h>

// Problem dims
#define BB 4
#define TT 2048
#define DD 1024
#define VV 32000
#define NTOK (BB * TT)                       // 8192
#define NLOGITS (262144000LL)                // NTOK * VV

// ---------------- scratch (device globals; no allocs allowed) ----------------
__device__ float g_h[NTOK * DD];             // 32 MB
__device__ float g_q[NTOK * DD];
__device__ float g_k[NTOK * DD];
__device__ float g_v[NTOK * DD];
__device__ float g_att[(long long)BB * TT * TT];  // 64 MB
__device__ float g_y[NTOK * DD];
__device__ float g_rowloss[NTOK];

// ---------------- embedding: h = tok_emb[x] + pos_emb[t] ----------------
__global__ void embed_kernel(const int* __restrict__ x,
                             const float* __restrict__ tok,
                             const float* __restrict__ pos,
                             float* __restrict__ h) {
    int i = blockIdx.x * blockDim.x + threadIdx.x;    // over NTOK*DD
    if (i >= NTOK * DD) return;
    int row = i >> 10;            // token index (DD = 1024)
    int d   = i & 1023;
    int t   = row & (TT - 1);
    int tid = x[row];
    h[i] = tok[(long long)tid * DD + d] + pos[t * DD + d];
}

// ---------------- tiled fp32 GEMM: C = alpha * A @ B(^T) + bias ----------------
// A: [M,K] row-major. B: row-major [K,N] (TRANSB=false) or [N,K] (TRANSB=true).
// BM=BN=128, BK=8, 256 threads, 8x8 per thread.
template <bool TRANSB>
__global__ __launch_bounds__(256)
void sgemm_kernel(const float* __restrict__ A, const float* __restrict__ B,
                  const float* __restrict__ bias, float* __restrict__ C,
                  int M, int N, int K, float alpha,
                  long long sA, long long sB, long long sC) {
    __shared__ float As[8][128];
    __shared__ float Bs[8][128];

    A += blockIdx.z * sA;
    B += blockIdx.z * sB;
    C += blockIdx.z * sC;

    const int m0 = blockIdx.y * 128;
    const int n0 = blockIdx.x * 128;
    const int tid = threadIdx.x;
    const int tr = tid >> 4;          // 0..15
    const int tc = tid & 15;          // 0..15

    const int aRow = tid >> 1;        // 0..127
    const int aCol = (tid & 1) * 4;   // 0 or 4

    float acc[8][8];
#pragma unroll
    for (int i = 0; i < 8; i++)
#pragma unroll
        for (int j = 0; j < 8; j++) acc[i][j] = 0.0f;

    for (int k0 = 0; k0 < K; k0 += 8) {
        // A tile (always transposed into smem)
        float4 av = *(const float4*)&A[(long long)(m0 + aRow) * K + k0 + aCol];
        As[aCol + 0][aRow] = av.x;
        As[aCol + 1][aRow] = av.y;
        As[aCol + 2][aRow] = av.z;
        As[aCol + 3][aRow] = av.w;

        if (!TRANSB) {
            int bRow = tid >> 5;              // 0..7   (K dim)
            int bCol = (tid & 31) * 4;        // 0..124 (N dim)
            float4 bv = *(const float4*)&B[(long long)(k0 + bRow) * N + n0 + bCol];
            *(float4*)&Bs[bRow][bCol] = bv;
        } else {
            int bRow = tid >> 1;              // 0..127 (N dim)
            int bCol = (tid & 1) * 4;         // K dim
            float4 bv = *(const float4*)&B[(long long)(n0 + bRow) * K + k0 + bCol];
            Bs[bCol + 0][bRow] = bv.x;
            Bs[bCol + 1][bRow] = bv.y;
            Bs[bCol + 2][bRow] = bv.z;
            Bs[bCol + 3][bRow] = bv.w;
        }
        __syncthreads();

#pragma unroll
        for (int k = 0; k < 8; k++) {
            float ra[8], rb[8];
            *(float4*)&ra[0] = *(const float4*)&As[k][tr * 8];
            *(float4*)&ra[4] = *(const float4*)&As[k][tr * 8 + 4];
            *(float4*)&rb[0] = *(const float4*)&Bs[k][tc * 8];
            *(float4*)&rb[4] = *(const float4*)&Bs[k][tc * 8 + 4];
#pragma unroll
            for (int i = 0; i < 8; i++)
#pragma unroll
                for (int j = 0; j < 8; j++) acc[i][j] += ra[i] * rb[j];
        }
        __syncthreads();
    }

    // epilogue
#pragma unroll
    for (int i = 0; i < 8; i++) {
        long long crow = (long long)(m0 + tr * 8 + i) * N + n0 + tc * 8;
#pragma unroll
        for (int j = 0; j < 8; j += 4) {
            float4 o;
            float b0 = bias ? bias[n0 + tc * 8 + j + 0] : 0.0f;
            float b1 = bias ? bias[n0 + tc * 8 + j + 1] : 0.0f;
            float b2 = bias ? bias[n0 + tc * 8 + j + 2] : 0.0f;
            float b3 = bias ? bias[n0 + tc * 8 + j + 3] : 0.0f;
            o.x = alpha * acc[i][j + 0] + b0;
            o.y = alpha * acc[i][j + 1] + b1;
            o.z = alpha * acc[i][j + 2] + b2;
            o.w = alpha * acc[i][j + 3] + b3;
            *(float4*)&C[crow + j] = o;
        }
    }
}

// ---------------- block reductions ----------------
__device__ __forceinline__ float blockMax(float v, float* red) {
#pragma unroll
    for (int o = 16; o; o >>= 1) v = fmaxf(v, __shfl_xor_sync(0xffffffffu, v, o));
    if ((threadIdx.x & 31) == 0) red[threadIdx.x >> 5] = v;
    __syncthreads();
    float r = red[0];
#pragma unroll
    for (int i = 1; i < 8; i++) r = fmaxf(r, red[i]);
    __syncthreads();
    return r;
}

__device__ __forceinline__ float blockSum(float v, float* red) {
#pragma unroll
    for (int o = 16; o; o >>= 1) v += __shfl_xor_sync(0xffffffffu, v, o);
    if ((threadIdx.x & 31) == 0) red[threadIdx.x >> 5] = v;
    __syncthreads();
    float r = red[0];
#pragma unroll
    for (int i = 1; i < 8; i++) r += red[i];
    __syncthreads();
    return r;
}

// ---------------- causal softmax over scores rows ----------------
__global__ __launch_bounds__(256)
void causal_softmax_kernel(float* __restrict__ att) {
    __shared__ float red[8];
    int row = blockIdx.x;                 // 0 .. B*T-1
    int i = row & (TT - 1);               // valid columns: 0..i
    float* p = att + (long long)row * TT;
    int tid = threadIdx.x;

    float m = -INFINITY;
    for (int j = tid; j <= i; j += 256) m = fmaxf(m, p[j]);
    m = blockMax(m, red);

    float s = 0.0f;
    for (int j = tid; j <= i; j += 256) {
        float e = expf(p[j] - m);
        p[j] = e;
        s += e;
    }
    s = blockSum(s, red);
    float inv = 1.0f / s;
    for (int j = tid; j <= i; j += 256) p[j] *= inv;
    for (int j = i + 1 + tid; j < TT; j += 256) p[j] = 0.0f;
}

// ---------------- per-row cross-entropy from logits ----------------
__global__ __launch_bounds__(256)
void rowloss_kernel(const float* __restrict__ logits,
                    const int* __restrict__ target,
                    float* __restrict__ rowloss) {
    __shared__ float red[8];
    int row = blockIdx.x;
    const float* p = logits + (long long)row * VV;
    int tid = threadIdx.x;

    float m = -INFINITY;
    for (int j = tid; j < VV; j += 256) m = fmaxf(m, p[j]);
    m = blockMax(m, red);

    float s = 0.0f;
    for (int j = tid; j < VV; j += 256) s += expf(p[j] - m);
    s = blockSum(s, red);

    if (tid == 0) rowloss[row] = m + logf(s) - p[target[row]];
}

__global__ __launch_bounds__(256)
void loss_reduce_kernel(const float* __restrict__ rowloss, float* __restrict__ out) {
    __shared__ float red[8];
    float s = 0.0f;
    for (int r = threadIdx.x; r < NTOK; r += 256) s += rowloss[r];
    s = blockSum(s, red);
    if (threadIdx.x == 0) out[0] = s / (float)NTOK;
}

// ---------------- launch ----------------
extern "C" void kernel_launch(void* const* d_in, const int* in_sizes, int n_in,
                              void* d_out, int out_size) {
    const int*   x      = (const int*)d_in[0];
    const int*   target = (const int*)d_in[1];
    const float* tok    = (const float*)d_in[2];
    const float* pos    = (const float*)d_in[3];
    const float* Wq     = (const float*)d_in[4];
    const float* bq     = (const float*)d_in[5];
    const float* Wk     = (const float*)d_in[6];
    const float* bk     = (const float*)d_in[7];
    const float* Wv     = (const float*)d_in[8];
    const float* bv     = (const float*)d_in[9];
    const float* W_lm   = (const float*)d_in[10];
    const float* b_lm   = (const float*)d_in[11];
    float* out = (float*)d_out;

    float *h, *q, *k, *v, *att, *y, *rowloss;
    cudaGetSymbolAddress((void**)&h,       g_h);
    cudaGetSymbolAddress((void**)&q,       g_q);
    cudaGetSymbolAddress((void**)&k,       g_k);
    cudaGetSymbolAddress((void**)&v,       g_v);
    cudaGetSymbolAddress((void**)&att,     g_att);
    cudaGetSymbolAddress((void**)&y,       g_y);
    cudaGetSymbolAddress((void**)&rowloss, g_rowloss);

    // 1. embedding
    embed_kernel<<<(NTOK * DD + 255) / 256, 256>>>(x, tok, pos, h);

    // 2. QKV projections: [8192,1024] @ [1024,1024]
    {
        dim3 grid(DD / 128, NTOK / 128, 1);
        sgemm_kernel<false><<<grid, 256>>>(h, Wq, bq, q, NTOK, DD, DD, 1.0f, 0, 0, 0);
        sgemm_kernel<false><<<grid, 256>>>(h, Wk, bk, k, NTOK, DD, DD, 1.0f, 0, 0, 0);
        sgemm_kernel<false><<<grid, 256>>>(h, Wv, bv, v, NTOK, DD, DD, 1.0f, 0, 0, 0);
    }

    // 3. scores = (q @ k^T) * D^-0.5, batched over B
    {
        dim3 grid(TT / 128, TT / 128, BB);
        sgemm_kernel<true><<<grid, 256>>>(q, k, nullptr, att, TT, TT, DD, 0.03125f,
                                          (long long)TT * DD, (long long)TT * DD,
                                          (long long)TT * TT);
    }

    // 4. causal softmax
    causal_softmax_kernel<<<NTOK, 256>>>(att);

    // 5. y = attn @ v, batched over B
    {
        dim3 grid(DD / 128, TT / 128, BB);
        sgemm_kernel<false><<<grid, 256>>>(att, v, nullptr, y, TT, DD, TT, 1.0f,
                                           (long long)TT * TT, (long long)TT * DD,
                                           (long long)TT * DD);
    }

    // 6. logits = y @ W_lm + b_lm  -> directly into d_out
    {
        dim3 grid(VV / 128, NTOK / 128, 1);
        sgemm_kernel<false><<<grid, 256>>>(y, W_lm, b_lm, out, NTOK, VV, DD, 1.0f, 0, 0, 0);
    }

    // 7. loss
    rowloss_kernel<<<NTOK, 256>>>(out, target, rowloss);
    if ((long long)out_size > NLOGITS) {
        loss_reduce_kernel<<<1, 256>>>(rowloss, out + NLOGITS);
    }
}

// round 3
// speedup vs baseline: 3.1402x; 3.1402x over previous
#include <cuda_runtime.h>
#include <cuda_bf16.h>
#include <math.h>
#include <stdint.h>

// ---------------- problem dims ----------------
#define BB 4
#define TT 2048
#define DD 1024
#define VV 32000
#define NTOK (BB * TT)                 // 8192
#define NLOGITS 262144000LL            // NTOK * VV
#define ATT_ELEMS ((long long)BB * TT * TT)

// ---------------- GEMM tiling ----------------
#define BM 128
#define BN 128
#define BKC 64          // bf16 K elems per chunk = 128 B rows (SW128)
#define GROUP_M 8
#define GEMM_THREADS 256
#define S_STAGES 3

#define STAGE_BYTES 65536               // Ahi 16K + Alo 16K + Bhi 16K + Blo 16K
#define OFF_AHI 0
#define OFF_ALO 16384
#define OFF_BHI 32768
#define OFF_BLO 49152
#define SMEM_TOTAL (S_STAGES * STAGE_BYTES)   // 196608

// ---------------- scratch (device globals) ----------------
__device__ __nv_bfloat16 g_h_hi[NTOK * DD],  g_h_lo[NTOK * DD];
__device__ __nv_bfloat16 g_q_hi[NTOK * DD],  g_q_lo[NTOK * DD];
__device__ __nv_bfloat16 g_k_hi[NTOK * DD],  g_k_lo[NTOK * DD];
__device__ float         g_v[NTOK * DD];
__device__ __nv_bfloat16 g_vT_hi[NTOK * DD], g_vT_lo[NTOK * DD];
__device__ float         g_att[ATT_ELEMS];
__device__ __nv_bfloat16 g_att_hi[ATT_ELEMS], g_att_lo[ATT_ELEMS];
__device__ __nv_bfloat16 g_y_hi[NTOK * DD],  g_y_lo[NTOK * DD];
__device__ __nv_bfloat16 g_WqT_hi[DD * DD],  g_WqT_lo[DD * DD];
__device__ __nv_bfloat16 g_WkT_hi[DD * DD],  g_WkT_lo[DD * DD];
__device__ __nv_bfloat16 g_WvT_hi[DD * DD],  g_WvT_lo[DD * DD];
__device__ __nv_bfloat16 g_WlmT_hi[(long long)VV * DD], g_WlmT_lo[(long long)VV * DD];
__device__ float         g_rowloss[NTOK];

// ---------------- helpers ----------------
__device__ __forceinline__ uint32_t smem_u32(const void* p) {
    uint32_t a;
    asm("{ .reg .u64 t; cvta.to.shared.u64 t, %1; cvt.u32.u64 %0, t; }" : "=r"(a) : "l"(p));
    return a;
}
__device__ __forceinline__ void cp16(uint32_t dst, const void* src) {
    asm volatile("cp.async.cg.shared.global [%0], [%1], 16;" :: "r"(dst), "l"(src));
}
__device__ __forceinline__ void ldsm_x4(uint32_t* r, uint32_t addr) {
    asm volatile("ldmatrix.sync.aligned.m8n8.x4.shared.b16 {%0,%1,%2,%3}, [%4];"
                 : "=r"(r[0]), "=r"(r[1]), "=r"(r[2]), "=r"(r[3]) : "r"(addr));
}
__device__ __forceinline__ void ldsm_x2(uint32_t* r, uint32_t addr) {
    asm volatile("ldmatrix.sync.aligned.m8n8.x2.shared.b16 {%0,%1}, [%2];"
                 : "=r"(r[0]), "=r"(r[1]) : "r"(addr));
}
__device__ __forceinline__ void mma_bf16(float* c, const uint32_t* a, const uint32_t* b) {
    asm volatile("mma.sync.aligned.m16n8k16.row.col.f32.bf16.bf16.f32 "
                 "{%0,%1,%2,%3}, {%4,%5,%6,%7}, {%8,%9}, {%0,%1,%2,%3};"
                 : "+f"(c[0]), "+f"(c[1]), "+f"(c[2]), "+f"(c[3])
                 : "r"(a[0]), "r"(a[1]), "r"(a[2]), "r"(a[3]), "r"(b[0]), "r"(b[1]));
}
__device__ __forceinline__ void split_bf16(float x, __nv_bfloat16& hi, __nv_bfloat16& lo) {
    hi = __float2bfloat16(x);
    lo = __float2bfloat16(x - __bfloat162float(hi));
}
#define SWZ(off) ((off) ^ (((off) >> 3) & 0x70))

// ---------------- split-bf16 HMMA GEMM ----------------
// C[M,N] = alpha * A[M,K] @ B[N,K]^T + bias. A,B given as (hi,lo) bf16 K-major.
template <bool SPLIT_OUT>
__global__ void __launch_bounds__(GEMM_THREADS, 1)
mmagemm(const __nv_bfloat16* __restrict__ Ahi, const __nv_bfloat16* __restrict__ Alo,
        const __nv_bfloat16* __restrict__ Bhi, const __nv_bfloat16* __restrict__ Blo,
        const float* __restrict__ bias, float alpha,
        float* __restrict__ C, __nv_bfloat16* __restrict__ Chi, __nv_bfloat16* __restrict__ Clo,
        int M, int N, int K,
        long long sA, long long sB, long long sC) {
    extern __shared__ char smem[];
    const uint32_t sb = smem_u32(smem);
    const int tid = threadIdx.x;
    const int wid = tid >> 5, lane = tid & 31;
    const int wm = wid >> 2, wn = wid & 3;      // 2 x 4 warps

    Ahi += blockIdx.z * sA;  Alo += blockIdx.z * sA;
    Bhi += blockIdx.z * sB;  Blo += blockIdx.z * sB;
    if (SPLIT_OUT) { Chi += blockIdx.z * sC; Clo += blockIdx.z * sC; }
    else           { C   += blockIdx.z * sC; }

    // L2 rasterization
    const int npn = N / BN, npm = M / BM;
    int pid = blockIdx.x;
    int group = GROUP_M * npn;
    int gid = pid / group;
    int first = gid * GROUP_M;
    int gsz = min(GROUP_M, npm - first);
    const int m0 = (first + (pid % gsz)) * BM;
    const int n0 = ((pid % group) / gsz) * BN;

    const int NC = K / BKC;

    auto load_stage = [&](int chunk, int stage) {
        const uint32_t st = sb + stage * STAGE_BYTES;
        const int kk = chunk * BKC;
#pragma unroll
        for (int it = 0; it < 4; it++) {
            int idx = tid + it * 256;
            int row = idx >> 3, ch = idx & 7;
            uint32_t dst = st + (uint32_t)(row * 128 + ((ch ^ (row & 7)) * 16));
            long long ga = (long long)(m0 + row) * K + kk + ch * 8;
            cp16(dst + OFF_AHI, Ahi + ga);
            cp16(dst + OFF_ALO, Alo + ga);
            long long gb = (long long)(n0 + row) * K + kk + ch * 8;
            cp16(dst + OFF_BHI, Bhi + gb);
            cp16(dst + OFF_BLO, Blo + gb);
        }
        asm volatile("cp.async.commit_group;" ::: "memory");
    };

    float acc[4][4][4];
#pragma unroll
    for (int a = 0; a < 4; a++)
#pragma unroll
        for (int b = 0; b < 4; b++)
#pragma unroll
            for (int c = 0; c < 4; c++) acc[a][b][c] = 0.0f;

    load_stage(0, 0);
    load_stage(1, 1);

    for (int i = 0; i < NC; i++) {
        if (i + 1 < NC) asm volatile("cp.async.wait_group 1;" ::: "memory");
        else            asm volatile("cp.async.wait_group 0;" ::: "memory");
        __syncthreads();

        const uint32_t st = sb + (i % S_STAGES) * STAGE_BYTES;
#pragma unroll
        for (int ks = 0; ks < 4; ks++) {
            uint32_t ah[4][4], al[4][4], bh[4][2], bl[4][2];
#pragma unroll
            for (int mt = 0; mt < 4; mt++) {
                int row = wm * 64 + mt * 16 + (lane & 15);
                uint32_t off = (uint32_t)(row * 128 + ks * 32 + ((lane >> 4) * 16));
                off = SWZ(off);
                ldsm_x4(ah[mt], st + OFF_AHI + off);
                ldsm_x4(al[mt], st + OFF_ALO + off);
            }
#pragma unroll
            for (int nt = 0; nt < 4; nt++) {
                int row = wn * 32 + nt * 8 + (lane & 7);
                uint32_t off = (uint32_t)(row * 128 + ks * 32 + (((lane >> 3) & 1) * 16));
                off = SWZ(off);
                ldsm_x2(bh[nt], st + OFF_BHI + off);
                ldsm_x2(bl[nt], st + OFF_BLO + off);
            }
#pragma unroll
            for (int mt = 0; mt < 4; mt++)
#pragma unroll
                for (int nt = 0; nt < 4; nt++) {
                    mma_bf16(acc[mt][nt], ah[mt], bh[nt]);
                    mma_bf16(acc[mt][nt], ah[mt], bl[nt]);
                    mma_bf16(acc[mt][nt], al[mt], bh[nt]);
                }
        }
        __syncthreads();
        if (i + 2 < NC) load_stage(i + 2, (i + 2) % S_STAGES);
    }

    // epilogue
    const int tg = lane >> 2;           // 0..7
    const int tc = (lane & 3) * 2;
#pragma unroll
    for (int mt = 0; mt < 4; mt++) {
#pragma unroll
        for (int nt = 0; nt < 4; nt++) {
            int r0 = m0 + wm * 64 + mt * 16 + tg;
            int c0 = n0 + wn * 32 + nt * 8 + tc;
            float b0 = bias ? bias[c0] : 0.0f;
            float b1 = bias ? bias[c0 + 1] : 0.0f;
            float v0 = alpha * acc[mt][nt][0] + b0;
            float v1 = alpha * acc[mt][nt][1] + b1;
            float v2 = alpha * acc[mt][nt][2] + b0;
            float v3 = alpha * acc[mt][nt][3] + b1;
            if (SPLIT_OUT) {
                __nv_bfloat16 h0, l0, h1, l1;
                split_bf16(v0, h0, l0); split_bf16(v1, h1, l1);
                *(__nv_bfloat162*)(Chi + (long long)r0 * N + c0) = __nv_bfloat162(h0, h1);
                *(__nv_bfloat162*)(Clo + (long long)r0 * N + c0) = __nv_bfloat162(l0, l1);
                split_bf16(v2, h0, l0); split_bf16(v3, h1, l1);
                *(__nv_bfloat162*)(Chi + (long long)(r0 + 8) * N + c0) = __nv_bfloat162(h0, h1);
                *(__nv_bfloat162*)(Clo + (long long)(r0 + 8) * N + c0) = __nv_bfloat162(l0, l1);
            } else {
                *(float2*)(C + (long long)r0 * N + c0) = make_float2(v0, v1);
                *(float2*)(C + (long long)(r0 + 8) * N + c0) = make_float2(v2, v3);
            }
        }
    }
}

// ---------------- embedding with split output ----------------
__global__ void embed_split_kernel(const int* __restrict__ x,
                                   const float* __restrict__ tok,
                                   const float* __restrict__ pos,
                                   __nv_bfloat16* __restrict__ hhi,
                                   __nv_bfloat16* __restrict__ hlo) {
    int i = blockIdx.x * blockDim.x + threadIdx.x;
    if (i >= NTOK * DD) return;
    int row = i >> 10;
    int d = i & 1023;
    int t = row & (TT - 1);
    float v = tok[(long long)x[row] * DD + d] + pos[t * DD + d];
    __nv_bfloat16 hi, lo;
    split_bf16(v, hi, lo);
    hhi[i] = hi; hlo[i] = lo;
}

// ---------------- transpose + split: in[R,C] fp32 -> out[C,R] bf16 hi/lo ----------------
__global__ void transpose_split_kernel(const float* __restrict__ in,
                                       __nv_bfloat16* __restrict__ ohi,
                                       __nv_bfloat16* __restrict__ olo,
                                       int R, int C, long long sIn, long long sOut) {
    __shared__ float tbuf[32][33];
    in += blockIdx.z * sIn;
    ohi += blockIdx.z * sOut;
    olo += blockIdx.z * sOut;
    int c0 = blockIdx.x * 32, r0 = blockIdx.y * 32;
    int tx = threadIdx.x, ty = threadIdx.y;
#pragma unroll
    for (int i = 0; i < 32; i += 8)
        tbuf[ty + i][tx] = in[(long long)(r0 + ty + i) * C + c0 + tx];
    __syncthreads();
#pragma unroll
    for (int i = 0; i < 32; i += 8) {
        float v = tbuf[tx][ty + i];
        __nv_bfloat16 hi, lo;
        split_bf16(v, hi, lo);
        long long o = (long long)(c0 + ty + i) * R + r0 + tx;
        ohi[o] = hi; olo[o] = lo;
    }
}

// ---------------- reductions ----------------
__device__ __forceinline__ float blockMax(float v, float* red) {
#pragma unroll
    for (int o = 16; o; o >>= 1) v = fmaxf(v, __shfl_xor_sync(0xffffffffu, v, o));
    if ((threadIdx.x & 31) == 0) red[threadIdx.x >> 5] = v;
    __syncthreads();
    float r = red[0];
#pragma unroll
    for (int i = 1; i < 8; i++) r = fmaxf(r, red[i]);
    __syncthreads();
    return r;
}
__device__ __forceinline__ float blockSum(float v, float* red) {
#pragma unroll
    for (int o = 16; o; o >>= 1) v += __shfl_xor_sync(0xffffffffu, v, o);
    if ((threadIdx.x & 31) == 0) red[threadIdx.x >> 5] = v;
    __syncthreads();
    float r = red[0];
#pragma unroll
    for (int i = 1; i < 8; i++) r += red[i];
    __syncthreads();
    return r;
}

// ---------------- causal softmax, split bf16 output ----------------
__global__ void __launch_bounds__(256)
softmax_split_kernel(const float* __restrict__ att,
                     __nv_bfloat16* __restrict__ ahi, __nv_bfloat16* __restrict__ alo) {
    __shared__ float red[8];
    int row = blockIdx.x;
    int i = row & (TT - 1);
    const float* p = att + (long long)row * TT;
    __nv_bfloat16* ph = ahi + (long long)row * TT;
    __nv_bfloat16* pl = alo + (long long)row * TT;
    int tid = threadIdx.x;

    float m = -INFINITY;
    for (int j = tid; j <= i; j += 256) m = fmaxf(m, p[j]);
    m = blockMax(m, red);

    float s = 0.0f;
    for (int j = tid; j <= i; j += 256) s += expf(p[j] - m);
    s = blockSum(s, red);
    float inv = 1.0f / s;

    for (int j = tid; j <= i; j += 256) {
        float e = expf(p[j] - m) * inv;
        __nv_bfloat16 hi, lo;
        split_bf16(e, hi, lo);
        ph[j] = hi; pl[j] = lo;
    }
    __nv_bfloat16 z = __float2bfloat16(0.0f);
    for (int j = i + 1 + tid; j < TT; j += 256) { ph[j] = z; pl[j] = z; }
}

// ---------------- loss ----------------
__global__ void __launch_bounds__(256)
rowloss_kernel(const float* __restrict__ logits, const int* __restrict__ target,
               float* __restrict__ rowloss) {
    __shared__ float red[8];
    int row = blockIdx.x;
    const float* p = logits + (long long)row * VV;
    int tid = threadIdx.x;
    float m = -INFINITY;
    for (int j = tid; j < VV; j += 256) m = fmaxf(m, p[j]);
    m = blockMax(m, red);
    float s = 0.0f;
    for (int j = tid; j < VV; j += 256) s += expf(p[j] - m);
    s = blockSum(s, red);
    if (tid == 0) rowloss[row] = m + logf(s) - p[target[row]];
}

__global__ void __launch_bounds__(256)
loss_reduce_kernel(const float* __restrict__ rowloss, float* __restrict__ out) {
    __shared__ float red[8];
    float s = 0.0f;
    for (int r = threadIdx.x; r < NTOK; r += 256) s += rowloss[r];
    s = blockSum(s, red);
    if (threadIdx.x == 0) out[0] = s / (float)NTOK;
}

// ---------------- launch ----------------
extern "C" void kernel_launch(void* const* d_in, const int* in_sizes, int n_in,
                              void* d_out, int out_size) {
    const int*   x      = (const int*)d_in[0];
    const int*   target = (const int*)d_in[1];
    const float* tok    = (const float*)d_in[2];
    const float* pos    = (const float*)d_in[3];
    const float* Wq     = (const float*)d_in[4];
    const float* bq     = (const float*)d_in[5];
    const float* Wk     = (const float*)d_in[6];
    const float* bk     = (const float*)d_in[7];
    const float* Wv     = (const float*)d_in[8];
    const float* bv     = (const float*)d_in[9];
    const float* W_lm   = (const float*)d_in[10];
    const float* b_lm   = (const float*)d_in[11];
    float* out = (float*)d_out;

    cudaFuncSetAttribute(mmagemm<false>, cudaFuncAttributeMaxDynamicSharedMemorySize, SMEM_TOTAL);
    cudaFuncSetAttribute(mmagemm<true>,  cudaFuncAttributeMaxDynamicSharedMemorySize, SMEM_TOTAL);

    __nv_bfloat16 *h_hi, *h_lo, *q_hi, *q_lo, *k_hi, *k_lo, *vT_hi, *vT_lo;
    __nv_bfloat16 *att_hi, *att_lo, *y_hi, *y_lo;
    __nv_bfloat16 *WqT_hi, *WqT_lo, *WkT_hi, *WkT_lo, *WvT_hi, *WvT_lo, *WlmT_hi, *WlmT_lo;
    float *v, *att, *rowloss;
    cudaGetSymbolAddress((void**)&h_hi, g_h_hi);   cudaGetSymbolAddress((void**)&h_lo, g_h_lo);
    cudaGetSymbolAddress((void**)&q_hi, g_q_hi);   cudaGetSymbolAddress((void**)&q_lo, g_q_lo);
    cudaGetSymbolAddress((void**)&k_hi, g_k_hi);   cudaGetSymbolAddress((void**)&k_lo, g_k_lo);
    cudaGetSymbolAddress((void**)&v, g_v);
    cudaGetSymbolAddress((void**)&vT_hi, g_vT_hi); cudaGetSymbolAddress((void**)&vT_lo, g_vT_lo);
    cudaGetSymbolAddress((void**)&att, g_att);
    cudaGetSymbolAddress((void**)&att_hi, g_att_hi); cudaGetSymbolAddress((void**)&att_lo, g_att_lo);
    cudaGetSymbolAddress((void**)&y_hi, g_y_hi);   cudaGetSymbolAddress((void**)&y_lo, g_y_lo);
    cudaGetSymbolAddress((void**)&WqT_hi, g_WqT_hi); cudaGetSymbolAddress((void**)&WqT_lo, g_WqT_lo);
    cudaGetSymbolAddress((void**)&WkT_hi, g_WkT_hi); cudaGetSymbolAddress((void**)&WkT_lo, g_WkT_lo);
    cudaGetSymbolAddress((void**)&WvT_hi, g_WvT_hi); cudaGetSymbolAddress((void**)&WvT_lo, g_WvT_lo);
    cudaGetSymbolAddress((void**)&WlmT_hi, g_WlmT_hi); cudaGetSymbolAddress((void**)&WlmT_lo, g_WlmT_lo);
    cudaGetSymbolAddress((void**)&rowloss, g_rowloss);

    dim3 tb(32, 8);

    // 1. embedding (split bf16)
    embed_split_kernel<<<(NTOK * DD + 255) / 256, 256>>>(x, tok, pos, h_hi, h_lo);

    // 2. weight transposes + splits
    transpose_split_kernel<<<dim3(DD / 32, DD / 32, 1), tb>>>(Wq, WqT_hi, WqT_lo, DD, DD, 0, 0);
    transpose_split_kernel<<<dim3(DD / 32, DD / 32, 1), tb>>>(Wk, WkT_hi, WkT_lo, DD, DD, 0, 0);
    transpose_split_kernel<<<dim3(DD / 32, DD / 32, 1), tb>>>(Wv, WvT_hi, WvT_lo, DD, DD, 0, 0);
    transpose_split_kernel<<<dim3(VV / 32, DD / 32, 1), tb>>>(W_lm, WlmT_hi, WlmT_lo, DD, VV, 0, 0);

    // 3. QKV projections [8192,1024] x [1024,1024]
    {
        dim3 grid((NTOK / BM) * (DD / BN), 1, 1);
        mmagemm<true><<<grid, GEMM_THREADS, SMEM_TOTAL>>>(h_hi, h_lo, WqT_hi, WqT_lo, bq, 1.0f,
            nullptr, q_hi, q_lo, NTOK, DD, DD, 0, 0, 0);
        mmagemm<true><<<grid, GEMM_THREADS, SMEM_TOTAL>>>(h_hi, h_lo, WkT_hi, WkT_lo, bk, 1.0f,
            nullptr, k_hi, k_lo, NTOK, DD, DD, 0, 0, 0);
        mmagemm<false><<<grid, GEMM_THREADS, SMEM_TOTAL>>>(h_hi, h_lo, WvT_hi, WvT_lo, bv, 1.0f,
            v, nullptr, nullptr, NTOK, DD, DD, 0, 0, 0);
    }

    // 4. v transpose per batch: [2048,1024] -> [1024,2048]
    transpose_split_kernel<<<dim3(DD / 32, TT / 32, BB), tb>>>(v, vT_hi, vT_lo, TT, DD,
        (long long)TT * DD, (long long)TT * DD);

    // 5. scores = q @ k^T * D^-0.5 (batched)
    {
        dim3 grid((TT / BM) * (TT / BN), 1, BB);
        mmagemm<false><<<grid, GEMM_THREADS, SMEM_TOTAL>>>(q_hi, q_lo, k_hi, k_lo, nullptr, 0.03125f,
            att, nullptr, nullptr, TT, TT, DD,
            (long long)TT * DD, (long long)TT * DD, (long long)TT * TT);
    }

    // 6. causal softmax -> split bf16
    softmax_split_kernel<<<NTOK, 256>>>(att, att_hi, att_lo);

    // 7. y = attn @ v (batched): B = vT [1024, 2048]
    {
        dim3 grid((TT / BM) * (DD / BN), 1, BB);
        mmagemm<true><<<grid, GEMM_THREADS, SMEM_TOTAL>>>(att_hi, att_lo, vT_hi, vT_lo, nullptr, 1.0f,
            nullptr, y_hi, y_lo, TT, DD, TT,
            (long long)TT * TT, (long long)TT * DD, (long long)TT * DD);
    }

    // 8. logits = y @ W_lm + b_lm -> d_out
    {
        dim3 grid((NTOK / BM) * (VV / BN), 1, 1);
        mmagemm<false><<<grid, GEMM_THREADS, SMEM_TOTAL>>>(y_hi, y_lo, WlmT_hi, WlmT_lo, b_lm, 1.0f,
            out, nullptr, nullptr, NTOK, VV, DD, 0, 0, 0);
    }

    // 9. loss
    rowloss_kernel<<<NTOK, 256>>>(out, target, rowloss);
    if ((long long)out_size > NLOGITS) {
        loss_reduce_kernel<<<1, 256>>>(rowloss, out + NLOGITS);
    }
}

// round 4
// speedup vs baseline: 4.2902x; 1.3662x over previous
#include <cuda_runtime.h>
#include <cuda_fp16.h>
#include <math.h>
#include <stdint.h>

// ---------------- problem dims ----------------
#define BB 4
#define TT 2048
#define DD 1024
#define VV 32000
#define NTOK (BB * TT)                 // 8192
#define NLOGITS 262144000LL
#define ATT_ELEMS ((long long)BB * TT * TT)

// ---------------- GEMM tiling ----------------
#define BM 128
#define BN 128
#define BKC 64          // fp16 K elems per chunk = 128 B rows
#define GROUP_M 8
#define GEMM_THREADS 256
#define S_STAGES 3

#define STAGE_BYTES 65536
#define OFF_AHI 0
#define OFF_ALO 16384
#define OFF_BHI 32768
#define OFF_BLO 49152
#define SMEM_TOTAL (S_STAGES * STAGE_BYTES)   // 196608

// ---------------- scratch ----------------
__device__ __half g_h_hi[NTOK * DD],  g_h_lo[NTOK * DD];
__device__ __half g_q_hi[NTOK * DD],  g_q_lo[NTOK * DD];
__device__ __half g_k_hi[NTOK * DD],  g_k_lo[NTOK * DD];
__device__ float  g_v[NTOK * DD];
__device__ __half g_vT_hi[NTOK * DD], g_vT_lo[NTOK * DD];
__device__ float  g_att[ATT_ELEMS];
__device__ __half g_att_hi[ATT_ELEMS], g_att_lo[ATT_ELEMS];
__device__ __half g_y_hi[NTOK * DD],  g_y_lo[NTOK * DD];
__device__ __half g_WqT_hi[DD * DD],  g_WqT_lo[DD * DD];
__device__ __half g_WkT_hi[DD * DD],  g_WkT_lo[DD * DD];
__device__ __half g_WvT_hi[DD * DD],  g_WvT_lo[DD * DD];
__device__ __half g_WlmT_hi[(long long)VV * DD], g_WlmT_lo[(long long)VV * DD];
__device__ float  g_rowloss[NTOK];

// ---------------- helpers ----------------
__device__ __forceinline__ uint32_t smem_u32(const void* p) {
    uint32_t a;
    asm("{ .reg .u64 t; cvta.to.shared.u64 t, %1; cvt.u32.u64 %0, t; }" : "=r"(a) : "l"(p));
    return a;
}
__device__ __forceinline__ void cp16(uint32_t dst, const void* src) {
    asm volatile("cp.async.cg.shared.global [%0], [%1], 16;" :: "r"(dst), "l"(src));
}
__device__ __forceinline__ void ldsm_x4(uint32_t* r, uint32_t addr) {
    asm volatile("ldmatrix.sync.aligned.m8n8.x4.shared.b16 {%0,%1,%2,%3}, [%4];"
                 : "=r"(r[0]), "=r"(r[1]), "=r"(r[2]), "=r"(r[3]) : "r"(addr));
}
__device__ __forceinline__ void ldsm_x2(uint32_t* r, uint32_t addr) {
    asm volatile("ldmatrix.sync.aligned.m8n8.x2.shared.b16 {%0,%1}, [%2];"
                 : "=r"(r[0]), "=r"(r[1]) : "r"(addr));
}
__device__ __forceinline__ void mma_fp16(float* c, const uint32_t* a, const uint32_t* b) {
    asm volatile("mma.sync.aligned.m16n8k16.row.col.f32.f16.f16.f32 "
                 "{%0,%1,%2,%3}, {%4,%5,%6,%7}, {%8,%9}, {%0,%1,%2,%3};"
                 : "+f"(c[0]), "+f"(c[1]), "+f"(c[2]), "+f"(c[3])
                 : "r"(a[0]), "r"(a[1]), "r"(a[2]), "r"(a[3]), "r"(b[0]), "r"(b[1]));
}
__device__ __forceinline__ void split_h(float x, __half& hi, __half& lo) {
    hi = __float2half_rn(x);
    lo = __float2half_rn(x - __half2float(hi));
}

// ---------------- split-fp16 HMMA GEMM ----------------
// MODE 0: normal. MODE 1: lower-triangular tile map (scores). MODE 2: K truncated at m0+BM.
// NPASS 3: hh + h*lo + lo*h.  NPASS 2: hh + h*Blo (A-lo skipped entirely).
template <int MODE, int NPASS, bool SPLIT_OUT>
__global__ void __launch_bounds__(GEMM_THREADS, 1)
mmagemm(const __half* __restrict__ Ahi, const __half* __restrict__ Alo,
        const __half* __restrict__ Bhi, const __half* __restrict__ Blo,
        const float* __restrict__ bias, float alpha,
        float* __restrict__ C, __half* __restrict__ Chi, __half* __restrict__ Clo,
        int M, int N, int K,
        long long sA, long long sB, long long sC) {
    extern __shared__ char smem[];
    const uint32_t sb = smem_u32(smem);
    const int tid = threadIdx.x;
    const int wid = tid >> 5, lane = tid & 31;
    const int wm = wid >> 2, wn = wid & 3;

    Ahi += blockIdx.z * sA;  if (NPASS == 3) Alo += blockIdx.z * sA;
    Bhi += blockIdx.z * sB;  Blo += blockIdx.z * sB;
    if (SPLIT_OUT) { Chi += blockIdx.z * sC; Clo += blockIdx.z * sC; }
    else           { C   += blockIdx.z * sC; }

    int m0, n0;
    if (MODE == 1) {
        int idx = blockIdx.x;
        int row = (int)((sqrtf(8.0f * idx + 1.0f) - 1.0f) * 0.5f);
        while ((row + 1) * (row + 2) / 2 <= idx) ++row;
        while (row * (row + 1) / 2 > idx) --row;
        int col = idx - row * (row + 1) / 2;
        m0 = row * BM; n0 = col * BN;
    } else {
        const int npn = N / BN, npm = M / BM;
        int pid = blockIdx.x;
        int group = GROUP_M * npn;
        int gid = pid / group;
        int first = gid * GROUP_M;
        int gsz = min(GROUP_M, npm - first);
        m0 = (first + (pid % gsz)) * BM;
        n0 = ((pid % group) / gsz) * BN;
    }

    int NC = K / BKC;
    if (MODE == 2) NC = min(NC, (m0 + BM) / BKC);

    auto load_stage = [&](int chunk, int stage) {
        const uint32_t st = sb + stage * STAGE_BYTES;
        const int kk = chunk * BKC;
#pragma unroll
        for (int it = 0; it < 4; it++) {
            int idx = tid + it * 256;
            int row = idx >> 3, ch = idx & 7;
            uint32_t dst = st + (uint32_t)(row * 128 + ((ch ^ (row & 7)) * 16));
            long long ga = (long long)(m0 + row) * K + kk + ch * 8;
            cp16(dst + OFF_AHI, Ahi + ga);
            if (NPASS == 3) cp16(dst + OFF_ALO, Alo + ga);
            long long gb = (long long)(n0 + row) * K + kk + ch * 8;
            cp16(dst + OFF_BHI, Bhi + gb);
            cp16(dst + OFF_BLO, Blo + gb);
        }
        asm volatile("cp.async.commit_group;" ::: "memory");
    };

    float acc[4][4][4];
#pragma unroll
    for (int a = 0; a < 4; a++)
#pragma unroll
        for (int b = 0; b < 4; b++)
#pragma unroll
            for (int c = 0; c < 4; c++) acc[a][b][c] = 0.0f;

    load_stage(0, 0);
    load_stage(1, 1);

    for (int i = 0; i < NC; i++) {
        if (i + 1 < NC) asm volatile("cp.async.wait_group 1;" ::: "memory");
        else            asm volatile("cp.async.wait_group 0;" ::: "memory");
        __syncthreads();

        const uint32_t st = sb + (i % S_STAGES) * STAGE_BYTES;
#pragma unroll
        for (int ks = 0; ks < 4; ks++) {
            uint32_t ah[4][4], al[4][4], bh[4][2], bl[4][2];
#pragma unroll
            for (int mt = 0; mt < 4; mt++) {
                int row = wm * 64 + mt * 16 + (lane & 15);
                uint32_t off = (uint32_t)(row * 128 + ks * 32 + ((lane >> 4) * 16));
                off = off ^ ((off >> 3) & 0x70);
                ldsm_x4(ah[mt], st + OFF_AHI + off);
                if (NPASS == 3) ldsm_x4(al[mt], st + OFF_ALO + off);
            }
#pragma unroll
            for (int nt = 0; nt < 4; nt++) {
                int row = wn * 32 + nt * 8 + (lane & 7);
                uint32_t off = (uint32_t)(row * 128 + ks * 32 + (((lane >> 3) & 1) * 16));
                off = off ^ ((off >> 3) & 0x70);
                ldsm_x2(bh[nt], st + OFF_BHI + off);
                ldsm_x2(bl[nt], st + OFF_BLO + off);
            }
#pragma unroll
            for (int mt = 0; mt < 4; mt++)
#pragma unroll
                for (int nt = 0; nt < 4; nt++) {
                    mma_fp16(acc[mt][nt], ah[mt], bh[nt]);
                    mma_fp16(acc[mt][nt], ah[mt], bl[nt]);
                    if (NPASS == 3) mma_fp16(acc[mt][nt], al[mt], bh[nt]);
                }
        }
        __syncthreads();
        if (i + 2 < NC) load_stage(i + 2, (i + 2) % S_STAGES);
    }

    // epilogue
    const int tg = lane >> 2;
    const int tc = (lane & 3) * 2;
#pragma unroll
    for (int mt = 0; mt < 4; mt++) {
#pragma unroll
        for (int nt = 0; nt < 4; nt++) {
            int r0 = m0 + wm * 64 + mt * 16 + tg;
            int c0 = n0 + wn * 32 + nt * 8 + tc;
            float b0 = bias ? bias[c0] : 0.0f;
            float b1 = bias ? bias[c0 + 1] : 0.0f;
            float v0 = alpha * acc[mt][nt][0] + b0;
            float v1 = alpha * acc[mt][nt][1] + b1;
            float v2 = alpha * acc[mt][nt][2] + b0;
            float v3 = alpha * acc[mt][nt][3] + b1;
            if (SPLIT_OUT) {
                __half h0, l0, h1, l1;
                split_h(v0, h0, l0); split_h(v1, h1, l1);
                *(__half2*)(Chi + (long long)r0 * N + c0) = __half2(h0, h1);
                *(__half2*)(Clo + (long long)r0 * N + c0) = __half2(l0, l1);
                split_h(v2, h0, l0); split_h(v3, h1, l1);
                *(__half2*)(Chi + (long long)(r0 + 8) * N + c0) = __half2(h0, h1);
                *(__half2*)(Clo + (long long)(r0 + 8) * N + c0) = __half2(l0, l1);
            } else {
                *(float2*)(C + (long long)r0 * N + c0) = make_float2(v0, v1);
                *(float2*)(C + (long long)(r0 + 8) * N + c0) = make_float2(v2, v3);
            }
        }
    }
}

// ---------------- embedding (split fp16) ----------------
__global__ void embed_split_kernel(const int* __restrict__ x,
                                   const float* __restrict__ tok,
                                   const float* __restrict__ pos,
                                   __half* __restrict__ hhi, __half* __restrict__ hlo) {
    int i = blockIdx.x * blockDim.x + threadIdx.x;
    if (i >= NTOK * DD) return;
    int row = i >> 10;
    int d = i & 1023;
    int t = row & (TT - 1);
    float v = tok[(long long)x[row] * DD + d] + pos[t * DD + d];
    __half hi, lo;
    split_h(v, hi, lo);
    hhi[i] = hi; hlo[i] = lo;
}

// ---------------- transpose + split ----------------
__global__ void transpose_split_kernel(const float* __restrict__ in,
                                       __half* __restrict__ ohi, __half* __restrict__ olo,
                                       int R, int C, long long sIn, long long sOut) {
    __shared__ float tbuf[32][33];
    in += blockIdx.z * sIn;
    ohi += blockIdx.z * sOut;
    olo += blockIdx.z * sOut;
    int c0 = blockIdx.x * 32, r0 = blockIdx.y * 32;
    int tx = threadIdx.x, ty = threadIdx.y;
#pragma unroll
    for (int i = 0; i < 32; i += 8)
        tbuf[ty + i][tx] = in[(long long)(r0 + ty + i) * C + c0 + tx];
    __syncthreads();
#pragma unroll
    for (int i = 0; i < 32; i += 8) {
        float v = tbuf[tx][ty + i];
        __half hi, lo;
        split_h(v, hi, lo);
        long long o = (long long)(c0 + ty + i) * R + r0 + tx;
        ohi[o] = hi; olo[o] = lo;
    }
}

// ---------------- reductions ----------------
__device__ __forceinline__ float blockMax(float v, float* red) {
#pragma unroll
    for (int o = 16; o; o >>= 1) v = fmaxf(v, __shfl_xor_sync(0xffffffffu, v, o));
    if ((threadIdx.x & 31) == 0) red[threadIdx.x >> 5] = v;
    __syncthreads();
    float r = red[0];
#pragma unroll
    for (int i = 1; i < 8; i++) r = fmaxf(r, red[i]);
    __syncthreads();
    return r;
}
__device__ __forceinline__ float blockSum(float v, float* red) {
#pragma unroll
    for (int o = 16; o; o >>= 1) v += __shfl_xor_sync(0xffffffffu, v, o);
    if ((threadIdx.x & 31) == 0) red[threadIdx.x >> 5] = v;
    __syncthreads();
    float r = red[0];
#pragma unroll
    for (int i = 1; i < 8; i++) r += red[i];
    __syncthreads();
    return r;
}

// ---------------- causal softmax -> split fp16 ----------------
__global__ void __launch_bounds__(256)
softmax_split_kernel(const float* __restrict__ att,
                     __half* __restrict__ ahi, __half* __restrict__ alo) {
    __shared__ float red[8];
    int row = blockIdx.x;
    int i = row & (TT - 1);
    const float* p = att + (long long)row * TT;
    __half* ph = ahi + (long long)row * TT;
    __half* pl = alo + (long long)row * TT;
    int tid = threadIdx.x;

    float m = -INFINITY;
    for (int j = tid; j <= i; j += 256) m = fmaxf(m, p[j]);
    m = blockMax(m, red);

    float s = 0.0f;
    for (int j = tid; j <= i; j += 256) s += expf(p[j] - m);
    s = blockSum(s, red);
    float inv = 1.0f / s;

    for (int j = tid; j <= i; j += 256) {
        float e = expf(p[j] - m) * inv;
        __half hi, lo;
        split_h(e, hi, lo);
        ph[j] = hi; pl[j] = lo;
    }
    __half z = __float2half(0.0f);
    for (int j = i + 1 + tid; j < TT; j += 256) { ph[j] = z; pl[j] = z; }
}

// ---------------- online single-pass row cross-entropy ----------------
__global__ void __launch_bounds__(256)
rowloss_kernel(const float* __restrict__ logits, const int* __restrict__ target,
               float* __restrict__ rowloss) {
    __shared__ float redm[8], reds[8];
    int row = blockIdx.x;
    const float4* p = (const float4*)(logits + (long long)row * VV);
    int tid = threadIdx.x;

    float m = -INFINITY, s = 0.0f;
    for (int j = tid; j < VV / 4; j += 256) {
        float4 v = p[j];
        float cm = fmaxf(fmaxf(v.x, v.y), fmaxf(v.z, v.w));
        if (cm > m) { s *= __expf(m - cm); m = cm; }
        s += __expf(v.x - m) + __expf(v.y - m) + __expf(v.z - m) + __expf(v.w - m);
    }
    // combine within warp
#pragma unroll
    for (int o = 16; o; o >>= 1) {
        float om = __shfl_xor_sync(0xffffffffu, m, o);
        float os = __shfl_xor_sync(0xffffffffu, s, o);
        float nm = fmaxf(m, om);
        s = s * __expf(m - nm) + os * __expf(om - nm);
        m = nm;
    }
    if ((tid & 31) == 0) { redm[tid >> 5] = m; reds[tid >> 5] = s; }
    __syncthreads();
    if (tid == 0) {
        float M = redm[0], S = reds[0];
#pragma unroll
        for (int i = 1; i < 8; i++) {
            float nm = fmaxf(M, redm[i]);
            S = S * __expf(M - nm) + reds[i] * __expf(redm[i] - nm);
            M = nm;
        }
        rowloss[row] = M + logf(S) - logits[(long long)row * VV + target[row]];
    }
}

__global__ void __launch_bounds__(256)
loss_reduce_kernel(const float* __restrict__ rowloss, float* __restrict__ out) {
    __shared__ float red[8];
    float s = 0.0f;
    for (int r = threadIdx.x; r < NTOK; r += 256) s += rowloss[r];
    s = blockSum(s, red);
    if (threadIdx.x == 0) out[0] = s / (float)NTOK;
}

// ---------------- launch ----------------
extern "C" void kernel_launch(void* const* d_in, const int* in_sizes, int n_in,
                              void* d_out, int out_size) {
    const int*   x      = (const int*)d_in[0];
    const int*   target = (const int*)d_in[1];
    const float* tok    = (const float*)d_in[2];
    const float* pos    = (const float*)d_in[3];
    const float* Wq     = (const float*)d_in[4];
    const float* bq     = (const float*)d_in[5];
    const float* Wk     = (const float*)d_in[6];
    const float* bk     = (const float*)d_in[7];
    const float* Wv     = (const float*)d_in[8];
    const float* bv     = (const float*)d_in[9];
    const float* W_lm   = (const float*)d_in[10];
    const float* b_lm   = (const float*)d_in[11];
    float* out = (float*)d_out;

    cudaFuncSetAttribute(mmagemm<0,3,false>, cudaFuncAttributeMaxDynamicSharedMemorySize, SMEM_TOTAL);
    cudaFuncSetAttribute(mmagemm<0,3,true>,  cudaFuncAttributeMaxDynamicSharedMemorySize, SMEM_TOTAL);
    cudaFuncSetAttribute(mmagemm<0,2,false>, cudaFuncAttributeMaxDynamicSharedMemorySize, SMEM_TOTAL);
    cudaFuncSetAttribute(mmagemm<1,3,false>, cudaFuncAttributeMaxDynamicSharedMemorySize, SMEM_TOTAL);
    cudaFuncSetAttribute(mmagemm<2,3,true>,  cudaFuncAttributeMaxDynamicSharedMemorySize, SMEM_TOTAL);

    __half *h_hi, *h_lo, *q_hi, *q_lo, *k_hi, *k_lo, *vT_hi, *vT_lo;
    __half *att_hi, *att_lo, *y_hi, *y_lo;
    __half *WqT_hi, *WqT_lo, *WkT_hi, *WkT_lo, *WvT_hi, *WvT_lo, *WlmT_hi, *WlmT_lo;
    float *v, *att, *rowloss;
    cudaGetSymbolAddress((void**)&h_hi, g_h_hi);   cudaGetSymbolAddress((void**)&h_lo, g_h_lo);
    cudaGetSymbolAddress((void**)&q_hi, g_q_hi);   cudaGetSymbolAddress((void**)&q_lo, g_q_lo);
    cudaGetSymbolAddress((void**)&k_hi, g_k_hi);   cudaGetSymbolAddress((void**)&k_lo, g_k_lo);
    cudaGetSymbolAddress((void**)&v, g_v);
    cudaGetSymbolAddress((void**)&vT_hi, g_vT_hi); cudaGetSymbolAddress((void**)&vT_lo, g_vT_lo);
    cudaGetSymbolAddress((void**)&att, g_att);
    cudaGetSymbolAddress((void**)&att_hi, g_att_hi); cudaGetSymbolAddress((void**)&att_lo, g_att_lo);
    cudaGetSymbolAddress((void**)&y_hi, g_y_hi);   cudaGetSymbolAddress((void**)&y_lo, g_y_lo);
    cudaGetSymbolAddress((void**)&WqT_hi, g_WqT_hi); cudaGetSymbolAddress((void**)&WqT_lo, g_WqT_lo);
    cudaGetSymbolAddress((void**)&WkT_hi, g_WkT_hi); cudaGetSymbolAddress((void**)&WkT_lo, g_WkT_lo);
    cudaGetSymbolAddress((void**)&WvT_hi, g_WvT_hi); cudaGetSymbolAddress((void**)&WvT_lo, g_WvT_lo);
    cudaGetSymbolAddress((void**)&WlmT_hi, g_WlmT_hi); cudaGetSymbolAddress((void**)&WlmT_lo, g_WlmT_lo);
    cudaGetSymbolAddress((void**)&rowloss, g_rowloss);

    dim3 tb(32, 8);

    embed_split_kernel<<<(NTOK * DD + 255) / 256, 256>>>(x, tok, pos, h_hi, h_lo);

    transpose_split_kernel<<<dim3(DD / 32, DD / 32, 1), tb>>>(Wq, WqT_hi, WqT_lo, DD, DD, 0, 0);
    transpose_split_kernel<<<dim3(DD / 32, DD / 32, 1), tb>>>(Wk, WkT_hi, WkT_lo, DD, DD, 0, 0);
    transpose_split_kernel<<<dim3(DD / 32, DD / 32, 1), tb>>>(Wv, WvT_hi, WvT_lo, DD, DD, 0, 0);
    transpose_split_kernel<<<dim3(VV / 32, DD / 32, 1), tb>>>(W_lm, WlmT_hi, WlmT_lo, DD, VV, 0, 0);

    // QKV projections (3-pass fp16)
    {
        dim3 grid((NTOK / BM) * (DD / BN), 1, 1);
        mmagemm<0,3,true><<<grid, GEMM_THREADS, SMEM_TOTAL>>>(h_hi, h_lo, WqT_hi, WqT_lo, bq, 1.0f,
            nullptr, q_hi, q_lo, NTOK, DD, DD, 0, 0, 0);
        mmagemm<0,3,true><<<grid, GEMM_THREADS, SMEM_TOTAL>>>(h_hi, h_lo, WkT_hi, WkT_lo, bk, 1.0f,
            nullptr, k_hi, k_lo, NTOK, DD, DD, 0, 0, 0);
        mmagemm<0,3,false><<<grid, GEMM_THREADS, SMEM_TOTAL>>>(h_hi, h_lo, WvT_hi, WvT_lo, bv, 1.0f,
            v, nullptr, nullptr, NTOK, DD, DD, 0, 0, 0);
    }

    transpose_split_kernel<<<dim3(DD / 32, TT / 32, BB), tb>>>(v, vT_hi, vT_lo, TT, DD,
        (long long)TT * DD, (long long)TT * DD);

    // scores: only lower-triangular tiles (136 per batch)
    {
        dim3 grid(136, 1, BB);
        mmagemm<1,3,false><<<grid, GEMM_THREADS, SMEM_TOTAL>>>(q_hi, q_lo, k_hi, k_lo, nullptr, 0.03125f,
            att, nullptr, nullptr, TT, TT, DD,
            (long long)TT * DD, (long long)TT * DD, (long long)TT * TT);
    }

    softmax_split_kernel<<<NTOK, 256>>>(att, att_hi, att_lo);

    // y = attn @ v, K truncated per M-tile
    {
        dim3 grid((TT / BM) * (DD / BN), 1, BB);
        mmagemm<2,3,true><<<grid, GEMM_THREADS, SMEM_TOTAL>>>(att_hi, att_lo, vT_hi, vT_lo, nullptr, 1.0f,
            nullptr, y_hi, y_lo, TT, DD, TT,
            (long long)TT * TT, (long long)TT * DD, (long long)TT * DD);
    }

    // logits = y @ W_lm + b_lm (2-pass fp16)
    {
        dim3 grid((NTOK / BM) * (VV / BN), 1, 1);
        mmagemm<0,2,false><<<grid, GEMM_THREADS, SMEM_TOTAL>>>(y_hi, y_lo, WlmT_hi, WlmT_lo, b_lm, 1.0f,
            out, nullptr, nullptr, NTOK, VV, DD, 0, 0, 0);
    }

    rowloss_kernel<<<NTOK, 256>>>(out, target, rowloss);
    if ((long long)out_size > NLOGITS) {
        loss_reduce_kernel<<<1, 256>>>(rowloss, out + NLOGITS);
    }
}

// round 5
// speedup vs baseline: 6.8302x; 1.5920x over previous
#include <cuda_runtime.h>
#include <cuda_fp16.h>
#include <math.h>
#include <stdint.h>

// ---------------- problem dims ----------------
#define BB 4
#define TT 2048
#define DD 1024
#define VV 32000
#define NTOK (BB * TT)                 // 8192
#define NLOGITS 262144000LL
#define ATT_ELEMS ((long long)BB * TT * TT)
#define LM_NTILES (VV / 128)           // 250

// ---------------- GEMM tiling ----------------
#define BM 128
#define BN 128
#define BKC 64
#define GROUP_M 8
#define GEMM_THREADS 256

// ---------------- scratch ----------------
__device__ __half g_h_hi[NTOK * DD],  g_h_lo[NTOK * DD];
__device__ __half g_q_hi[NTOK * DD],  g_q_lo[NTOK * DD];
__device__ __half g_k_hi[NTOK * DD],  g_k_lo[NTOK * DD];
__device__ float  g_v[NTOK * DD];
__device__ __half g_vT_hi[NTOK * DD], g_vT_lo[NTOK * DD];
__device__ float  g_att[ATT_ELEMS];
__device__ __half g_att_hi[ATT_ELEMS], g_att_lo[ATT_ELEMS];
__device__ __half g_y_hi[NTOK * DD];
__device__ __half g_WqT_hi[DD * DD],  g_WqT_lo[DD * DD];
__device__ __half g_WkT_hi[DD * DD],  g_WkT_lo[DD * DD];
__device__ __half g_WvT_hi[DD * DD],  g_WvT_lo[DD * DD];
__device__ __half g_WlmT_hi[(long long)VV * DD];
__device__ float  g_pm[(long long)NTOK * LM_NTILES];   // per-tile row max
__device__ float  g_ps[(long long)NTOK * LM_NTILES];   // per-tile row sumexp
__device__ float  g_rowloss[NTOK];

// ---------------- helpers ----------------
__device__ __forceinline__ uint32_t smem_u32(const void* p) {
    uint32_t a;
    asm("{ .reg .u64 t; cvta.to.shared.u64 t, %1; cvt.u32.u64 %0, t; }" : "=r"(a) : "l"(p));
    return a;
}
__device__ __forceinline__ void cp16(uint32_t dst, const void* src) {
    asm volatile("cp.async.cg.shared.global [%0], [%1], 16;" :: "r"(dst), "l"(src));
}
__device__ __forceinline__ void ldsm_x4(uint32_t* r, uint32_t addr) {
    asm volatile("ldmatrix.sync.aligned.m8n8.x4.shared.b16 {%0,%1,%2,%3}, [%4];"
                 : "=r"(r[0]), "=r"(r[1]), "=r"(r[2]), "=r"(r[3]) : "r"(addr));
}
__device__ __forceinline__ void ldsm_x2(uint32_t* r, uint32_t addr) {
    asm volatile("ldmatrix.sync.aligned.m8n8.x2.shared.b16 {%0,%1}, [%2];"
                 : "=r"(r[0]), "=r"(r[1]) : "r"(addr));
}
__device__ __forceinline__ void mma_fp16(float* c, const uint32_t* a, const uint32_t* b) {
    asm volatile("mma.sync.aligned.m16n8k16.row.col.f32.f16.f16.f32 "
                 "{%0,%1,%2,%3}, {%4,%5,%6,%7}, {%8,%9}, {%0,%1,%2,%3};"
                 : "+f"(c[0]), "+f"(c[1]), "+f"(c[2]), "+f"(c[3])
                 : "r"(a[0]), "r"(a[1]), "r"(a[2]), "r"(a[3]), "r"(b[0]), "r"(b[1]));
}
__device__ __forceinline__ void split_h(float x, __half& hi, __half& lo) {
    hi = __float2half_rn(x);
    lo = __float2half_rn(x - __half2float(hi));
}

// ---------------- split-fp16 HMMA GEMM ----------------
// MODE 0: normal. MODE 1: lower-triangular tiles. MODE 2: K truncated at m0+BM.
// NPASS 3: A(hi,lo),B(hi,lo): hh+h*lo+lo*h.  NPASS 2: A hi, B(hi,lo): hh+h*lo.  NPASS 1: hh only.
// OUTM 0: f32. OUTM 1: fp16 hi. OUTM 2: fp16 hi+lo.
// FUSE: also emit per-tile row (max, sumexp) partials (requires OUTM==0).
template <int MODE, int NPASS, int OUTM, bool FUSE>
__global__ void __launch_bounds__(GEMM_THREADS)
mmagemm(const __half* __restrict__ Ahi, const __half* __restrict__ Alo,
        const __half* __restrict__ Bhi, const __half* __restrict__ Blo,
        const float* __restrict__ bias, float alpha,
        float* __restrict__ C, __half* __restrict__ Chi, __half* __restrict__ Clo,
        float* __restrict__ pm, float* __restrict__ ps,
        int M, int N, int K,
        long long sA, long long sB, long long sC) {
    constexpr int NTILE = 16384;
    constexpr int T_AHI = 0;
    constexpr int T_ALO = (NPASS == 3) ? NTILE : 0;
    constexpr int T_BHI = (NPASS == 3) ? 2 * NTILE : NTILE;
    constexpr int T_BLO = T_BHI + NTILE;
    constexpr int STAGE = ((NPASS == 3) ? 4 : (NPASS == 2) ? 3 : 2) * NTILE;

    extern __shared__ char smem[];
    const uint32_t sb = smem_u32(smem);
    const int tid = threadIdx.x;
    const int wid = tid >> 5, lane = tid & 31;
    const int wm = wid >> 2, wn = wid & 3;

    Ahi += blockIdx.z * sA;  if (NPASS == 3) Alo += blockIdx.z * sA;
    Bhi += blockIdx.z * sB;  if (NPASS >= 2) Blo += blockIdx.z * sB;
    if (OUTM == 0) C += blockIdx.z * sC;
    else { Chi += blockIdx.z * sC; if (OUTM == 2) Clo += blockIdx.z * sC; }

    int m0, n0;
    if (MODE == 1) {
        int idx = blockIdx.x;
        int row = (int)((sqrtf(8.0f * idx + 1.0f) - 1.0f) * 0.5f);
        while ((row + 1) * (row + 2) / 2 <= idx) ++row;
        while (row * (row + 1) / 2 > idx) --row;
        int col = idx - row * (row + 1) / 2;
        m0 = row * BM; n0 = col * BN;
    } else {
        const int npn = N / BN, npm = M / BM;
        int pid = blockIdx.x;
        int group = GROUP_M * npn;
        int gid = pid / group;
        int first = gid * GROUP_M;
        int gsz = min(GROUP_M, npm - first);
        m0 = (first + (pid % gsz)) * BM;
        n0 = ((pid % group) / gsz) * BN;
    }

    int NC = K / BKC;
    if (MODE == 2) NC = min(NC, (m0 + BM) / BKC);

    auto load_stage = [&](int chunk, int stage) {
        const uint32_t st = sb + stage * STAGE;
        const int kk = chunk * BKC;
#pragma unroll
        for (int it = 0; it < 4; it++) {
            int idx = tid + it * 256;
            int row = idx >> 3, ch = idx & 7;
            uint32_t dst = st + (uint32_t)(row * 128 + ((ch ^ (row & 7)) * 16));
            long long ga = (long long)(m0 + row) * K + kk + ch * 8;
            cp16(dst + T_AHI, Ahi + ga);
            if (NPASS == 3) cp16(dst + T_ALO, Alo + ga);
            long long gb = (long long)(n0 + row) * K + kk + ch * 8;
            cp16(dst + T_BHI, Bhi + gb);
            if (NPASS >= 2) cp16(dst + T_BLO, Blo + gb);
        }
        asm volatile("cp.async.commit_group;" ::: "memory");
    };

    float acc[4][4][4];
#pragma unroll
    for (int a = 0; a < 4; a++)
#pragma unroll
        for (int b = 0; b < 4; b++)
#pragma unroll
            for (int c = 0; c < 4; c++) acc[a][b][c] = 0.0f;

    load_stage(0, 0);
    load_stage(1, 1);

    for (int i = 0; i < NC; i++) {
        if (i + 1 < NC) asm volatile("cp.async.wait_group 1;" ::: "memory");
        else            asm volatile("cp.async.wait_group 0;" ::: "memory");
        __syncthreads();

        const uint32_t st = sb + (i % 3) * STAGE;
#pragma unroll
        for (int ks = 0; ks < 4; ks++) {
            uint32_t ah[4][4], al[4][4], bh[4][2], bl[4][2];
#pragma unroll
            for (int mt = 0; mt < 4; mt++) {
                int row = wm * 64 + mt * 16 + (lane & 15);
                uint32_t off = (uint32_t)(row * 128 + ks * 32 + ((lane >> 4) * 16));
                off = off ^ ((off >> 3) & 0x70);
                ldsm_x4(ah[mt], st + T_AHI + off);
                if (NPASS == 3) ldsm_x4(al[mt], st + T_ALO + off);
            }
#pragma unroll
            for (int nt = 0; nt < 4; nt++) {
                int row = wn * 32 + nt * 8 + (lane & 7);
                uint32_t off = (uint32_t)(row * 128 + ks * 32 + (((lane >> 3) & 1) * 16));
                off = off ^ ((off >> 3) & 0x70);
                ldsm_x2(bh[nt], st + T_BHI + off);
                if (NPASS >= 2) ldsm_x2(bl[nt], st + T_BLO + off);
            }
#pragma unroll
            for (int mt = 0; mt < 4; mt++)
#pragma unroll
                for (int nt = 0; nt < 4; nt++) {
                    mma_fp16(acc[mt][nt], ah[mt], bh[nt]);
                    if (NPASS >= 2) mma_fp16(acc[mt][nt], ah[mt], bl[nt]);
                    if (NPASS == 3) mma_fp16(acc[mt][nt], al[mt], bh[nt]);
                }
        }
        __syncthreads();
        if (i + 2 < NC) load_stage(i + 2, (i + 2) % 3);
    }

    // finalize values (alpha, bias)
    const int tg = lane >> 2;
    const int tc = (lane & 3) * 2;
#pragma unroll
    for (int mt = 0; mt < 4; mt++)
#pragma unroll
        for (int nt = 0; nt < 4; nt++) {
            int c0 = n0 + wn * 32 + nt * 8 + tc;
            float b0 = bias ? bias[c0] : 0.0f;
            float b1 = bias ? bias[c0 + 1] : 0.0f;
            acc[mt][nt][0] = alpha * acc[mt][nt][0] + b0;
            acc[mt][nt][1] = alpha * acc[mt][nt][1] + b1;
            acc[mt][nt][2] = alpha * acc[mt][nt][2] + b0;
            acc[mt][nt][3] = alpha * acc[mt][nt][3] + b1;
        }

    // stores
#pragma unroll
    for (int mt = 0; mt < 4; mt++)
#pragma unroll
        for (int nt = 0; nt < 4; nt++) {
            int r0 = m0 + wm * 64 + mt * 16 + tg;
            int c0 = n0 + wn * 32 + nt * 8 + tc;
            if (OUTM == 0) {
                *(float2*)(C + (long long)r0 * N + c0) = make_float2(acc[mt][nt][0], acc[mt][nt][1]);
                *(float2*)(C + (long long)(r0 + 8) * N + c0) = make_float2(acc[mt][nt][2], acc[mt][nt][3]);
            } else if (OUTM == 1) {
                *(__half2*)(Chi + (long long)r0 * N + c0) =
                    __half2(__float2half_rn(acc[mt][nt][0]), __float2half_rn(acc[mt][nt][1]));
                *(__half2*)(Chi + (long long)(r0 + 8) * N + c0) =
                    __half2(__float2half_rn(acc[mt][nt][2]), __float2half_rn(acc[mt][nt][3]));
            } else {
                __half h0, l0, h1, l1;
                split_h(acc[mt][nt][0], h0, l0); split_h(acc[mt][nt][1], h1, l1);
                *(__half2*)(Chi + (long long)r0 * N + c0) = __half2(h0, h1);
                *(__half2*)(Clo + (long long)r0 * N + c0) = __half2(l0, l1);
                split_h(acc[mt][nt][2], h0, l0); split_h(acc[mt][nt][3], h1, l1);
                *(__half2*)(Chi + (long long)(r0 + 8) * N + c0) = __half2(h0, h1);
                *(__half2*)(Clo + (long long)(r0 + 8) * N + c0) = __half2(l0, l1);
            }
        }

    // fused per-tile row logsumexp partials
    if (FUSE) {
        float* smM = (float*)smem;            // [4][128]
        float* smS = smM + 512;               // [4][128]
        float rm[8], rs[8];
#pragma unroll
        for (int mt = 0; mt < 4; mt++)
#pragma unroll
            for (int hf = 0; hf < 2; hf++) {
                float m = -INFINITY;
#pragma unroll
                for (int nt = 0; nt < 4; nt++) {
                    m = fmaxf(m, acc[mt][nt][hf * 2 + 0]);
                    m = fmaxf(m, acc[mt][nt][hf * 2 + 1]);
                }
                rm[mt * 2 + hf] = m;
            }
#pragma unroll
        for (int s = 0; s < 8; s++) {
            rm[s] = fmaxf(rm[s], __shfl_xor_sync(0xffffffffu, rm[s], 1));
            rm[s] = fmaxf(rm[s], __shfl_xor_sync(0xffffffffu, rm[s], 2));
        }
#pragma unroll
        for (int mt = 0; mt < 4; mt++)
#pragma unroll
            for (int hf = 0; hf < 2; hf++) {
                float m = rm[mt * 2 + hf], s = 0.0f;
#pragma unroll
                for (int nt = 0; nt < 4; nt++) {
                    s += __expf(acc[mt][nt][hf * 2 + 0] - m);
                    s += __expf(acc[mt][nt][hf * 2 + 1] - m);
                }
                rs[mt * 2 + hf] = s;
            }
#pragma unroll
        for (int s = 0; s < 8; s++) {
            rs[s] += __shfl_xor_sync(0xffffffffu, rs[s], 1);
            rs[s] += __shfl_xor_sync(0xffffffffu, rs[s], 2);
        }
        if ((lane & 3) == 0) {
#pragma unroll
            for (int mt = 0; mt < 4; mt++)
#pragma unroll
                for (int hf = 0; hf < 2; hf++) {
                    int rin = wm * 64 + mt * 16 + hf * 8 + tg;
                    smM[wn * 128 + rin] = rm[mt * 2 + hf];
                    smS[wn * 128 + rin] = rs[mt * 2 + hf];
                }
        }
        __syncthreads();
        if (tid < 128) {
            float M = smM[tid];
            M = fmaxf(M, smM[128 + tid]);
            M = fmaxf(M, smM[256 + tid]);
            M = fmaxf(M, smM[384 + tid]);
            float S = smS[tid] * __expf(smM[tid] - M)
                    + smS[128 + tid] * __expf(smM[128 + tid] - M)
                    + smS[256 + tid] * __expf(smM[256 + tid] - M)
                    + smS[384 + tid] * __expf(smM[384 + tid] - M);
            long long o = (long long)(m0 + tid) * (N / BN) + n0 / BN;
            pm[o] = M; ps[o] = S;
        }
    }
}

// ---------------- embedding (split fp16) ----------------
__global__ void embed_split_kernel(const int* __restrict__ x,
                                   const float* __restrict__ tok,
                                   const float* __restrict__ pos,
                                   __half* __restrict__ hhi, __half* __restrict__ hlo) {
    int i = blockIdx.x * blockDim.x + threadIdx.x;
    if (i >= NTOK * DD) return;
    int row = i >> 10;
    int d = i & 1023;
    int t = row & (TT - 1);
    float v = tok[(long long)x[row] * DD + d] + pos[t * DD + d];
    __half hi, lo;
    split_h(v, hi, lo);
    hhi[i] = hi; hlo[i] = lo;
}

// ---------------- transpose + split (lo optional) ----------------
__global__ void transpose_split_kernel(const float* __restrict__ in,
                                       __half* __restrict__ ohi, __half* __restrict__ olo,
                                       int R, int C, long long sIn, long long sOut) {
    __shared__ float tbuf[32][33];
    in += blockIdx.z * sIn;
    ohi += blockIdx.z * sOut;
    if (olo) olo += blockIdx.z * sOut;
    int c0 = blockIdx.x * 32, r0 = blockIdx.y * 32;
    int tx = threadIdx.x, ty = threadIdx.y;
#pragma unroll
    for (int i = 0; i < 32; i += 8)
        tbuf[ty + i][tx] = in[(long long)(r0 + ty + i) * C + c0 + tx];
    __syncthreads();
#pragma unroll
    for (int i = 0; i < 32; i += 8) {
        float v = tbuf[tx][ty + i];
        long long o = (long long)(c0 + ty + i) * R + r0 + tx;
        if (olo) {
            __half hi, lo;
            split_h(v, hi, lo);
            ohi[o] = hi; olo[o] = lo;
        } else {
            ohi[o] = __float2half_rn(v);
        }
    }
}

// ---------------- reductions ----------------
__device__ __forceinline__ float blockMax(float v, float* red) {
#pragma unroll
    for (int o = 16; o; o >>= 1) v = fmaxf(v, __shfl_xor_sync(0xffffffffu, v, o));
    if ((threadIdx.x & 31) == 0) red[threadIdx.x >> 5] = v;
    __syncthreads();
    float r = red[0];
#pragma unroll
    for (int i = 1; i < 8; i++) r = fmaxf(r, red[i]);
    __syncthreads();
    return r;
}
__device__ __forceinline__ float blockSum(float v, float* red) {
#pragma unroll
    for (int o = 16; o; o >>= 1) v += __shfl_xor_sync(0xffffffffu, v, o);
    if ((threadIdx.x & 31) == 0) red[threadIdx.x >> 5] = v;
    __syncthreads();
    float r = red[0];
#pragma unroll
    for (int i = 1; i < 8; i++) r += red[i];
    __syncthreads();
    return r;
}

// ---------------- causal softmax -> split fp16 ----------------
__global__ void __launch_bounds__(256)
softmax_split_kernel(const float* __restrict__ att,
                     __half* __restrict__ ahi, __half* __restrict__ alo) {
    __shared__ float red[8];
    int row = blockIdx.x;
    int i = row & (TT - 1);
    const float* p = att + (long long)row * TT;
    __half* ph = ahi + (long long)row * TT;
    __half* pl = alo + (long long)row * TT;
    int tid = threadIdx.x;

    float m = -INFINITY;
    for (int j = tid; j <= i; j += 256) m = fmaxf(m, p[j]);
    m = blockMax(m, red);

    float s = 0.0f;
    for (int j = tid; j <= i; j += 256) s += expf(p[j] - m);
    s = blockSum(s, red);
    float inv = 1.0f / s;

    for (int j = tid; j <= i; j += 256) {
        float e = expf(p[j] - m) * inv;
        __half hi, lo;
        split_h(e, hi, lo);
        ph[j] = hi; pl[j] = lo;
    }
    __half z = __float2half(0.0f);
    for (int j = i + 1 + tid; j < TT; j += 256) { ph[j] = z; pl[j] = z; }
}

// ---------------- rowloss from fused partials ----------------
__global__ void __launch_bounds__(32)
rowloss_partials_kernel(const float* __restrict__ pm, const float* __restrict__ ps,
                        const float* __restrict__ logits, const int* __restrict__ target,
                        float* __restrict__ rowloss) {
    int row = blockIdx.x;
    int lane = threadIdx.x;
    float m = -INFINITY, s = 0.0f;
    for (int t = lane; t < LM_NTILES; t += 32) {
        long long o = (long long)row * LM_NTILES + t;
        float tm = pm[o], ts = ps[o];
        float nm = fmaxf(m, tm);
        s = s * __expf(m - nm) + ts * __expf(tm - nm);
        m = nm;
    }
#pragma unroll
    for (int o = 16; o; o >>= 1) {
        float om = __shfl_xor_sync(0xffffffffu, m, o);
        float os = __shfl_xor_sync(0xffffffffu, s, o);
        float nm = fmaxf(m, om);
        s = s * __expf(m - nm) + os * __expf(om - nm);
        m = nm;
    }
    if (lane == 0)
        rowloss[row] = m + logf(s) - logits[(long long)row * VV + target[row]];
}

__global__ void __launch_bounds__(256)
loss_reduce_kernel(const float* __restrict__ rowloss, float* __restrict__ out) {
    __shared__ float red[8];
    float s = 0.0f;
    for (int r = threadIdx.x; r < NTOK; r += 256) s += rowloss[r];
    s = blockSum(s, red);
    if (threadIdx.x == 0) out[0] = s / (float)NTOK;
}

// ---------------- launch ----------------
extern "C" void kernel_launch(void* const* d_in, const int* in_sizes, int n_in,
                              void* d_out, int out_size) {
    const int*   x      = (const int*)d_in[0];
    const int*   target = (const int*)d_in[1];
    const float* tok    = (const float*)d_in[2];
    const float* pos    = (const float*)d_in[3];
    const float* Wq     = (const float*)d_in[4];
    const float* bq     = (const float*)d_in[5];
    const float* Wk     = (const float*)d_in[6];
    const float* bk     = (const float*)d_in[7];
    const float* Wv     = (const float*)d_in[8];
    const float* bv     = (const float*)d_in[9];
    const float* W_lm   = (const float*)d_in[10];
    const float* b_lm   = (const float*)d_in[11];
    float* out = (float*)d_out;

    const int SM3 = 3 * 4 * 16384;   // 196608 (3-pass)
    const int SM2 = 3 * 3 * 16384;   // 147456 (2-pass)
    const int SM1 = 3 * 2 * 16384;   //  98304 (1-pass)

    cudaFuncSetAttribute((const void*)mmagemm<0,3,2,false>, cudaFuncAttributeMaxDynamicSharedMemorySize, SM3);
    cudaFuncSetAttribute((const void*)mmagemm<0,2,0,false>, cudaFuncAttributeMaxDynamicSharedMemorySize, SM2);
    cudaFuncSetAttribute((const void*)mmagemm<1,3,0,false>, cudaFuncAttributeMaxDynamicSharedMemorySize, SM3);
    cudaFuncSetAttribute((const void*)mmagemm<2,3,1,false>, cudaFuncAttributeMaxDynamicSharedMemorySize, SM3);
    cudaFuncSetAttribute((const void*)mmagemm<0,1,0,true>,  cudaFuncAttributeMaxDynamicSharedMemorySize, SM1);

    __half *h_hi, *h_lo, *q_hi, *q_lo, *k_hi, *k_lo, *vT_hi, *vT_lo;
    __half *att_hi, *att_lo, *y_hi;
    __half *WqT_hi, *WqT_lo, *WkT_hi, *WkT_lo, *WvT_hi, *WvT_lo, *WlmT_hi;
    float *v, *att, *rowloss, *pm, *ps;
    cudaGetSymbolAddress((void**)&h_hi, g_h_hi);   cudaGetSymbolAddress((void**)&h_lo, g_h_lo);
    cudaGetSymbolAddress((void**)&q_hi, g_q_hi);   cudaGetSymbolAddress((void**)&q_lo, g_q_lo);
    cudaGetSymbolAddress((void**)&k_hi, g_k_hi);   cudaGetSymbolAddress((void**)&k_lo, g_k_lo);
    cudaGetSymbolAddress((void**)&v, g_v);
    cudaGetSymbolAddress((void**)&vT_hi, g_vT_hi); cudaGetSymbolAddress((void**)&vT_lo, g_vT_lo);
    cudaGetSymbolAddress((void**)&att, g_att);
    cudaGetSymbolAddress((void**)&att_hi, g_att_hi); cudaGetSymbolAddress((void**)&att_lo, g_att_lo);
    cudaGetSymbolAddress((void**)&y_hi, g_y_hi);
    cudaGetSymbolAddress((void**)&WqT_hi, g_WqT_hi); cudaGetSymbolAddress((void**)&WqT_lo, g_WqT_lo);
    cudaGetSymbolAddress((void**)&WkT_hi, g_WkT_hi); cudaGetSymbolAddress((void**)&WkT_lo, g_WkT_lo);
    cudaGetSymbolAddress((void**)&WvT_hi, g_WvT_hi); cudaGetSymbolAddress((void**)&WvT_lo, g_WvT_lo);
    cudaGetSymbolAddress((void**)&WlmT_hi, g_WlmT_hi);
    cudaGetSymbolAddress((void**)&pm, g_pm);       cudaGetSymbolAddress((void**)&ps, g_ps);
    cudaGetSymbolAddress((void**)&rowloss, g_rowloss);

    dim3 tb(32, 8);

    embed_split_kernel<<<(NTOK * DD + 255) / 256, 256>>>(x, tok, pos, h_hi, h_lo);

    transpose_split_kernel<<<dim3(DD / 32, DD / 32, 1), tb>>>(Wq, WqT_hi, WqT_lo, DD, DD, 0, 0);
    transpose_split_kernel<<<dim3(DD / 32, DD / 32, 1), tb>>>(Wk, WkT_hi, WkT_lo, DD, DD, 0, 0);
    transpose_split_kernel<<<dim3(DD / 32, DD / 32, 1), tb>>>(Wv, WvT_hi, WvT_lo, DD, DD, 0, 0);
    transpose_split_kernel<<<dim3(VV / 32, DD / 32, 1), tb>>>(W_lm, WlmT_hi, nullptr, DD, VV, 0, 0);

    // q, k: 3-pass, split output (feed softmax path — protect precision)
    {
        dim3 grid((NTOK / BM) * (DD / BN), 1, 1);
        mmagemm<0,3,2,false><<<grid, GEMM_THREADS, SM3>>>(h_hi, h_lo, WqT_hi, WqT_lo, bq, 1.0f,
            nullptr, q_hi, q_lo, nullptr, nullptr, NTOK, DD, DD, 0, 0, 0);
        mmagemm<0,3,2,false><<<grid, GEMM_THREADS, SM3>>>(h_hi, h_lo, WkT_hi, WkT_lo, bk, 1.0f,
            nullptr, k_hi, k_lo, nullptr, nullptr, NTOK, DD, DD, 0, 0, 0);
        // v: 2-pass, fp32 out (linear path)
        mmagemm<0,2,0,false><<<grid, GEMM_THREADS, SM2>>>(h_hi, nullptr, WvT_hi, WvT_lo, bv, 1.0f,
            v, nullptr, nullptr, nullptr, nullptr, NTOK, DD, DD, 0, 0, 0);
    }

    transpose_split_kernel<<<dim3(DD / 32, TT / 32, BB), tb>>>(v, vT_hi, vT_lo, TT, DD,
        (long long)TT * DD, (long long)TT * DD);

    // scores: 3-pass, lower-triangular tiles only
    {
        dim3 grid(136, 1, BB);
        mmagemm<1,3,0,false><<<grid, GEMM_THREADS, SM3>>>(q_hi, q_lo, k_hi, k_lo, nullptr, 0.03125f,
            att, nullptr, nullptr, nullptr, nullptr, TT, TT, DD,
            (long long)TT * DD, (long long)TT * DD, (long long)TT * TT);
    }

    softmax_split_kernel<<<NTOK, 256>>>(att, att_hi, att_lo);

    // y = attn @ v: 3-pass, K truncated, hi-only output
    {
        dim3 grid((TT / BM) * (DD / BN), 1, BB);
        mmagemm<2,3,1,false><<<grid, GEMM_THREADS, SM3>>>(att_hi, att_lo, vT_hi, vT_lo, nullptr, 1.0f,
            nullptr, y_hi, nullptr, nullptr, nullptr, TT, DD, TT,
            (long long)TT * TT, (long long)TT * DD, (long long)TT * DD);
    }

    // logits: 1-pass pure fp16 + fused loss partials
    {
        dim3 grid((NTOK / BM) * (VV / BN), 1, 1);
        mmagemm<0,1,0,true><<<grid, GEMM_THREADS, SM1>>>(y_hi, nullptr, WlmT_hi, nullptr, b_lm, 1.0f,
            out, nullptr, nullptr, pm, ps, NTOK, VV, DD, 0, 0, 0);
    }

    rowloss_partials_kernel<<<NTOK, 32>>>(pm, ps, out, target, rowloss);
    if ((long long)out_size > NLOGITS) {
        loss_reduce_kernel<<<1, 256>>>(rowloss, out + NLOGITS);
    }
}